// round 7
// baseline (speedup 1.0000x reference)
#include <cuda_runtime.h>
#include <cstdint>

#define BB 4
#define SS 4096
#define DD 512
#define NR 32
#define QK_SCALE 0.04419417382415922f   // 1/sqrt(512)

// Scratch (no allocations allowed).
__device__ int   g_cols[SS * NR];
__device__ int   g_cnt[SS];
__device__ float g_prob[(size_t)BB * SS * NR];   // 2 MB

// ---------------------------------------------------------------------------
// Mask dtype probe. Row 0 has ONLY col 0 true; row 1 has cols {0,1} true.
// ---------------------------------------------------------------------------
__device__ __forceinline__ int detect_code(const unsigned char* __restrict__ m) {
    if (m[4096] == 1) return 0;
    const int* mi = (const int*)m;
    return (mi[4097] == 1) ? 1 : 2;
}

__device__ __forceinline__ unsigned nb_from_i4(int4 w) {
    return (w.x ? 1u : 0u) | (w.y ? 2u : 0u) | (w.z ? 4u : 0u) | (w.w ? 8u : 0u);
}

// ---------------------------------------------------------------------------
// Mask compaction: one warp per row; 4 independent 16B loads per lane per
// outer iter (MLP=4) feeding a deterministic warp-scan compaction.
// ---------------------------------------------------------------------------
__global__ void __launch_bounds__(256)
compact_kernel(const void* __restrict__ mask) {
    const int row  = blockIdx.x * 8 + (threadIdx.x >> 5);
    const int lane = threadIdx.x & 31;
    const int code = detect_code((const unsigned char*)mask);
    const size_t roff = (size_t)row * SS;

    int base = 0;
    #pragma unroll 1
    for (int it = 0; it < SS / 512; ++it) {            // 8 outer iters
        unsigned nbv[4];
        if (code == 0) {                               // 1-byte mask
            const unsigned* mb = (const unsigned*)((const unsigned char*)mask + roff)
                                 + it * 128 + lane * 4;
            unsigned w0 = mb[0], w1 = mb[1], w2 = mb[2], w3 = mb[3];
            unsigned m0 = __vsetne4(w0, 0u), m1 = __vsetne4(w1, 0u);
            unsigned m2 = __vsetne4(w2, 0u), m3 = __vsetne4(w3, 0u);
            nbv[0] = (m0 & 1u) | ((m0 >> 7) & 2u) | ((m0 >> 14) & 4u) | ((m0 >> 21) & 8u);
            nbv[1] = (m1 & 1u) | ((m1 >> 7) & 2u) | ((m1 >> 14) & 4u) | ((m1 >> 21) & 8u);
            nbv[2] = (m2 & 1u) | ((m2 >> 7) & 2u) | ((m2 >> 14) & 4u) | ((m2 >> 21) & 8u);
            nbv[3] = (m3 & 1u) | ((m3 >> 7) & 2u) | ((m3 >> 14) & 4u) | ((m3 >> 21) & 8u);
        } else {                                       // 4-byte mask
            const int4* mi = (const int4*)((const int*)mask + roff) + it * 128 + lane;
            nbv[0] = nb_from_i4(mi[0]);  nbv[1] = nb_from_i4(mi[32]);
            nbv[2] = nb_from_i4(mi[64]); nbv[3] = nb_from_i4(mi[96]);
        }
        #pragma unroll
        for (int p = 0; p < 4; ++p) {
            const unsigned nb = nbv[p];
            const int c4 = __popc(nb);
            int x = c4;                                // inclusive warp scan
            #pragma unroll
            for (int off = 1; off < 32; off <<= 1) {
                int y = __shfl_up_sync(0xffffffffu, x, off);
                if (lane >= off) x += y;
            }
            int pos = base + x - c4;
            const int col0 = it * 512 + p * 128 + lane * 4;
            #pragma unroll
            for (int b = 0; b < 4; ++b)
                if ((nb >> b) & 1u) {
                    if (pos < NR) g_cols[row * NR + pos] = col0 + b;
                    ++pos;
                }
            base += __shfl_sync(0xffffffffu, x, 31);
        }
    }
    if (lane == 0) g_cnt[row] = (base < NR) ? base : NR;
}

// ---------------------------------------------------------------------------
// Sparse attention (R4 two-pass body, unmodified compute). One warp per
// (b, query row). Probabilities stashed in g_prob for the deferred scatter.
// ---------------------------------------------------------------------------
__global__ void __launch_bounds__(256, 2)
attn_kernel(const float* __restrict__ q, const float* __restrict__ k,
            const float* __restrict__ v, float* __restrict__ out) {
    const int warp  = blockIdx.x * 8 + (threadIdx.x >> 5);
    const int lane  = threadIdx.x & 31;
    const int wslot = threadIdx.x >> 5;
    const int b = warp >> 12;
    const int i = warp & (SS - 1);

    __shared__ float s_p[8][NR];
    __shared__ int   s_col[8][NR];

    const int c = g_cnt[i];
    s_col[wslot][lane] = (lane < c) ? g_cols[i * NR + lane] : 0;
    __syncwarp();

    const float4* qr = (const float4*)(q + ((size_t)b * SS + i) * DD);
    const float4 qf0 = qr[lane];
    const float4 qf1 = qr[lane + 32];
    const float4 qf2 = qr[lane + 64];
    const float4 qf3 = qr[lane + 96];

    const float4* kb = (const float4*)(k + (size_t)b * SS * DD);
    const float4* vb = (const float4*)(v + (size_t)b * SS * DD);

#define QK_BODY(J)                                                            \
    {                                                                         \
        const int col = s_col[wslot][(J)];                                    \
        const float4* kr = kb + (size_t)col * (DD / 4);                       \
        const float4 k0 = kr[lane];                                           \
        const float4 k1 = kr[lane + 32];                                      \
        const float4 k2 = kr[lane + 64];                                      \
        const float4 k3 = kr[lane + 96];                                      \
        float d = qf0.x * k0.x + qf0.y * k0.y + qf0.z * k0.z + qf0.w * k0.w   \
                + qf1.x * k1.x + qf1.y * k1.y + qf1.z * k1.z + qf1.w * k1.w   \
                + qf2.x * k2.x + qf2.y * k2.y + qf2.z * k2.z + qf2.w * k2.w   \
                + qf3.x * k3.x + qf3.y * k3.y + qf3.z * k3.z + qf3.w * k3.w;  \
        _Pragma("unroll")                                                     \
        for (int off = 16; off; off >>= 1)                                    \
            d += __shfl_xor_sync(0xffffffffu, d, off);                        \
        if (lane == 0) s_p[wslot][(J)] = d * QK_SCALE;                        \
    }

#define AV_BODY(J)                                                            \
    {                                                                         \
        const float p = s_p[wslot][(J)];                                      \
        const float4* vr = vb + (size_t)s_col[wslot][(J)] * (DD / 4);         \
        const float4 v0 = vr[lane];                                           \
        const float4 v1 = vr[lane + 32];                                      \
        const float4 v2 = vr[lane + 64];                                      \
        const float4 v3 = vr[lane + 96];                                      \
        a0.x += p * v0.x; a0.y += p * v0.y; a0.z += p * v0.z; a0.w += p * v0.w;\
        a1.x += p * v1.x; a1.y += p * v1.y; a1.z += p * v1.z; a1.w += p * v1.w;\
        a2.x += p * v2.x; a2.y += p * v2.y; a2.z += p * v2.z; a2.w += p * v2.w;\
        a3.x += p * v3.x; a3.y += p * v3.y; a3.z += p * v3.z; a3.w += p * v3.w;\
    }

    if (c == 32) {
        #pragma unroll 2
        for (int j = 0; j < 32; ++j) QK_BODY(j)
    } else {
        for (int j = 0; j < c; ++j) QK_BODY(j)
    }
    __syncwarp();

    float m = -3.402823466e38f;
    for (int j = 0; j < c; ++j) m = fmaxf(m, s_p[wslot][j]);
    float e = (lane < c) ? __expf(s_p[wslot][lane] - m) : 0.0f;
    float sum = e;
    #pragma unroll
    for (int off = 16; off; off >>= 1)
        sum += __shfl_xor_sync(0xffffffffu, sum, off);
    const float inv = __frcp_rn(sum);
    const float p_l = e * inv;
    if (lane < c) s_p[wslot][lane] = p_l;
    g_prob[(size_t)warp * NR + lane] = p_l;     // stash for deferred scatter
    __syncwarp();

    float4 a0 = {0,0,0,0}, a1 = {0,0,0,0}, a2 = {0,0,0,0}, a3 = {0,0,0,0};
    if (c == 32) {
        #pragma unroll 2
        for (int j = 0; j < 32; ++j) AV_BODY(j)
    } else {
        for (int j = 0; j < c; ++j) AV_BODY(j)
    }
    float4* orow = (float4*)(out + ((size_t)b * SS + i) * DD);
    orow[lane]      = a0;
    orow[lane + 32] = a1;
    orow[lane + 64] = a2;
    orow[lane + 96] = a3;
#undef QK_BODY
#undef AV_BODY
}

// ---------------------------------------------------------------------------
// Deferred scatter over the (now fully zeroed) dense regions.
// ---------------------------------------------------------------------------
__global__ void __launch_bounds__(256)
scatter_kernel(float* __restrict__ attn_out, float* __restrict__ mask_out,
               int write_attn, int write_mask) {
    const int warp = blockIdx.x * 8 + (threadIdx.x >> 5);
    const int lane = threadIdx.x & 31;
    const int b = warp >> 12;
    const int i = warp & (SS - 1);
    const int c = g_cnt[i];
    if (lane >= c) return;
    const int col = g_cols[i * NR + lane];
    if (write_attn)
        attn_out[((size_t)b * SS + i) * SS + col] = g_prob[(size_t)warp * NR + lane];
    if (write_mask && b == 0)
        mask_out[(size_t)i * SS + col] = 1.0f;
}

// Side-stream machinery for concurrent memset. Created lazily on the FIRST
// kernel_launch call (the uncaptured correctness run), then reused during
// graph capture via the standard fork-join event pattern.
static cudaStream_t g_side = nullptr;
static cudaEvent_t  g_ev_fork = nullptr, g_ev_join = nullptr;
static int g_stream_ok = -1;

extern "C" void kernel_launch(void* const* d_in, const int* in_sizes, int n_in,
                              void* d_out, int out_size) {
    const float* q   = (const float*)d_in[0];
    const float* k   = (const float*)d_in[1];
    const float* v   = (const float*)d_in[2];
    const void*  msk = d_in[3];
    float* out = (float*)d_out;

    const size_t OUT_N  = (size_t)BB * SS * DD;   //  8,388,608
    const size_t ATTN_N = (size_t)BB * SS * SS;   // 67,108,864
    const size_t MASK_N = (size_t)SS * SS;        // 16,777,216

    const int write_attn = (size_t)out_size >= OUT_N + ATTN_N;
    const int write_mask = (size_t)out_size >= OUT_N + ATTN_N + MASK_N;
    const size_t tail_bytes = ((size_t)out_size > OUT_N)
        ? ((size_t)out_size - OUT_N) * sizeof(float) : 0;

    if (g_stream_ok < 0) {   // first call: uncaptured correctness run
        g_stream_ok =
            (cudaStreamCreateWithFlags(&g_side, cudaStreamNonBlocking) == cudaSuccess &&
             cudaEventCreateWithFlags(&g_ev_fork, cudaEventDisableTiming) == cudaSuccess &&
             cudaEventCreateWithFlags(&g_ev_join, cudaEventDisableTiming) == cudaSuccess)
            ? 1 : 0;
    }

    const bool fork = (g_stream_ok == 1) && tail_bytes > 0;

    if (fork) {
        // Fork: side stream zeroes the attn+mask region concurrently with
        // compact+attn on the main stream.
        cudaEventRecord(g_ev_fork, 0);
        cudaStreamWaitEvent(g_side, g_ev_fork, 0);
        cudaMemsetAsync(out + OUT_N, 0, tail_bytes, g_side);
        cudaEventRecord(g_ev_join, g_side);
    } else if (tail_bytes > 0) {
        cudaMemsetAsync(out + OUT_N, 0, tail_bytes);   // serial fallback
    }

    compact_kernel<<<SS / 8, 256>>>(msk);

    attn_kernel<<<(BB * SS) / 8, 256>>>(q, k, v, out);

    if (fork)
        cudaStreamWaitEvent(0, g_ev_join, 0);   // join before the scatter

    if (write_attn || write_mask)
        scatter_kernel<<<(BB * SS) / 8, 256>>>(
            write_attn ? (out + OUT_N) : nullptr,
            write_mask ? (out + OUT_N + ATTN_N) : nullptr,
            write_attn, write_mask);
}

// round 8
// speedup vs baseline: 1.0269x; 1.0269x over previous
#include <cuda_runtime.h>
#include <cstdint>

#define BB 4
#define SS 4096
#define DD 512
#define NR 32
#define QK_SCALE 0.04419417382415922f   // 1/sqrt(512)

// Scratch (no allocations allowed).
__device__ int   g_cols[SS * NR];
__device__ int   g_cnt[SS];
__device__ float g_prob[(size_t)BB * SS * NR];   // 2 MB

// ---------------------------------------------------------------------------
// Mask dtype probe. Row 0 has ONLY col 0 true; row 1 has cols {0,1} true.
//  byte[4096]: 1-byte storage -> (row1,col0)=1; 4-byte storage -> row0 -> 0.
//  word[4097]: int32 -> (row1,col1)=1; f32 -> 0x3F800000.
// ---------------------------------------------------------------------------
__device__ __forceinline__ int detect_code(const unsigned char* __restrict__ m) {
    if (m[4096] == 1) return 0;
    const int* mi = (const int*)m;
    return (mi[4097] == 1) ? 1 : 2;
}

__device__ __forceinline__ unsigned nib_from_u(unsigned w) {
    unsigned m = __vsetne4(w, 0u);     // 0x01 per nonzero byte
    return (m & 1u) | ((m >> 7) & 2u) | ((m >> 14) & 4u) | ((m >> 21) & 8u);
}
__device__ __forceinline__ unsigned nib_from_i4(int4 w) {
    return (w.x ? 1u : 0u) | (w.y ? 2u : 0u) | (w.z ? 4u : 0u) | (w.w ? 8u : 0u);
}

// ---------------------------------------------------------------------------
// Mask compaction, ballot-prefix version. One warp per row; each lane owns 16
// CONTIGUOUS columns per iter -> 16-bit truth mask, cnt<=16. Lane-prefix is
// computed with 5 independent ballots (one per cnt bit) + popc — no serial
// shfl-scan chain. Deterministic, sorted output.
// ---------------------------------------------------------------------------
__global__ void __launch_bounds__(256)
compact_kernel(const void* __restrict__ mask) {
    const int row  = blockIdx.x * 8 + (threadIdx.x >> 5);
    const int lane = threadIdx.x & 31;
    const int code = detect_code((const unsigned char*)mask);
    const unsigned lt = (1u << lane) - 1u;

    int base = 0;
    #pragma unroll 1
    for (int it = 0; it < SS / 512; ++it) {            // 8 iters, 512 cols each
        const int col0 = it * 512 + lane * 16;
        unsigned m16;
        if (code == 0) {                               // 1-byte mask
            const uint4 wv = *(const uint4*)((const unsigned char*)mask
                                             + (size_t)row * SS + col0);
            m16 = nib_from_u(wv.x) | (nib_from_u(wv.y) << 4)
                | (nib_from_u(wv.z) << 8) | (nib_from_u(wv.w) << 12);
        } else {                                       // 4-byte mask
            const int4* mi = (const int4*)((const int*)mask + (size_t)row * SS + col0);
            m16 = nib_from_i4(mi[0]) | (nib_from_i4(mi[1]) << 4)
                | (nib_from_i4(mi[2]) << 8) | (nib_from_i4(mi[3]) << 12);
        }
        const unsigned cnt = __popc(m16);
        const unsigned b0 = __ballot_sync(0xffffffffu, cnt & 1u);
        const unsigned b1 = __ballot_sync(0xffffffffu, cnt & 2u);
        const unsigned b2 = __ballot_sync(0xffffffffu, cnt & 4u);
        const unsigned b3 = __ballot_sync(0xffffffffu, cnt & 8u);
        const unsigned b4 = __ballot_sync(0xffffffffu, cnt & 16u);
        int pos = base
                + __popc(b0 & lt) + 2 * __popc(b1 & lt) + 4 * __popc(b2 & lt)
                + 8 * __popc(b3 & lt) + 16 * __popc(b4 & lt);
        unsigned mm = m16;
        while (mm) {
            const int bb = __ffs(mm) - 1;
            if (pos < NR) g_cols[row * NR + pos] = col0 + bb;
            ++pos;
            mm &= mm - 1u;
        }
        base += __popc(b0) + 2 * __popc(b1) + 4 * __popc(b2)
              + 8 * __popc(b3) + 16 * __popc(b4);
    }
    if (lane == 0) g_cnt[row] = (base < NR) ? base : NR;
}

// ---------------------------------------------------------------------------
// Sparse attention, warp-PAIR per query row (16 keys per warp). Halving the
// per-warp serial chain (dot -> 5-shfl butterfly -> exp, x16 instead of x32)
// improves latency hiding at unchanged register/occupancy cost. Scores meet
// in smem; partial V-accumulators combine through smem with one block sync.
// ---------------------------------------------------------------------------
__global__ void __launch_bounds__(256, 4)
attn_kernel(const float* __restrict__ q, const float* __restrict__ k,
            const float* __restrict__ v, float* __restrict__ out) {
    const int wslot = threadIdx.x >> 5;
    const int lane  = threadIdx.x & 31;
    const int w     = blockIdx.x * 8 + wslot;
    const int pair  = w >> 1;            // (b, i) id
    const int half  = w & 1;
    const int pslot = wslot >> 1;        // 0..3
    const int b = pair >> 12;
    const int i = pair & (SS - 1);

    __shared__ float  s_p[4][NR];
    __shared__ float4 s_acc[4][DD / 4];  // 8 KB

    const int c = g_cnt[i];
    const int col_l = (lane < c) ? g_cols[i * NR + lane] : 0;

    const float4* qr = (const float4*)(q + ((size_t)b * SS + i) * DD);
    const float4 qf0 = qr[lane];
    const float4 qf1 = qr[lane + 32];
    const float4 qf2 = qr[lane + 64];
    const float4 qf3 = qr[lane + 96];

    const float4* kb = (const float4*)(k + (size_t)b * SS * DD);
    const float4* vb = (const float4*)(v + (size_t)b * SS * DD);

    const int lo = half * 16;
    const int hi = (c < lo + 16) ? c : lo + 16;   // may be <= lo (idle half)

#define QK_BODY(J)                                                            \
    {                                                                         \
        const int col = __shfl_sync(0xffffffffu, col_l, (J));                 \
        const float4* kr = kb + (size_t)col * (DD / 4);                       \
        const float4 k0 = kr[lane];                                           \
        const float4 k1 = kr[lane + 32];                                      \
        const float4 k2 = kr[lane + 64];                                      \
        const float4 k3 = kr[lane + 96];                                      \
        float d = qf0.x * k0.x + qf0.y * k0.y + qf0.z * k0.z + qf0.w * k0.w   \
                + qf1.x * k1.x + qf1.y * k1.y + qf1.z * k1.z + qf1.w * k1.w   \
                + qf2.x * k2.x + qf2.y * k2.y + qf2.z * k2.z + qf2.w * k2.w   \
                + qf3.x * k3.x + qf3.y * k3.y + qf3.z * k3.z + qf3.w * k3.w;  \
        _Pragma("unroll")                                                     \
        for (int off = 16; off; off >>= 1)                                    \
            d += __shfl_xor_sync(0xffffffffu, d, off);                        \
        if (lane == 0) s_p[pslot][(J)] = d * QK_SCALE;                        \
    }

    if (c == 32) {
        #pragma unroll 2
        for (int t = 0; t < 16; ++t) QK_BODY(lo + t)
    } else {
        for (int j = lo; j < hi; ++j) QK_BODY(j)
    }
    __syncthreads();

    // --- softmax over c (<=32) scores (both halves compute identically) ---
    float sc = (lane < c) ? s_p[pslot][lane] : -3.402823466e38f;
    float m = sc;
    #pragma unroll
    for (int off = 16; off; off >>= 1)
        m = fmaxf(m, __shfl_xor_sync(0xffffffffu, m, off));
    const float e = (lane < c) ? __expf(sc - m) : 0.0f;
    float sum = e;
    #pragma unroll
    for (int off = 16; off; off >>= 1)
        sum += __shfl_xor_sync(0xffffffffu, sum, off);
    const float inv = __frcp_rn(sum);
    const float p_l = e * inv;
    if (half == 0)
        g_prob[(size_t)pair * NR + lane] = p_l;   // stash for the fill kernel

    // --- partial out = sum_{j in my half} p_j * V[col_j] ---
    float4 a0 = {0,0,0,0}, a1 = {0,0,0,0}, a2 = {0,0,0,0}, a3 = {0,0,0,0};
#define AV_BODY(J)                                                            \
    {                                                                         \
        const float p = __shfl_sync(0xffffffffu, p_l, (J));                   \
        const int col = __shfl_sync(0xffffffffu, col_l, (J));                 \
        const float4* vr = vb + (size_t)col * (DD / 4);                       \
        const float4 v0 = vr[lane];                                           \
        const float4 v1 = vr[lane + 32];                                      \
        const float4 v2 = vr[lane + 64];                                      \
        const float4 v3 = vr[lane + 96];                                      \
        a0.x += p * v0.x; a0.y += p * v0.y; a0.z += p * v0.z; a0.w += p * v0.w;\
        a1.x += p * v1.x; a1.y += p * v1.y; a1.z += p * v1.z; a1.w += p * v1.w;\
        a2.x += p * v2.x; a2.y += p * v2.y; a2.z += p * v2.z; a2.w += p * v2.w;\
        a3.x += p * v3.x; a3.y += p * v3.y; a3.z += p * v3.z; a3.w += p * v3.w;\
    }
    if (c == 32) {
        #pragma unroll 2
        for (int t = 0; t < 16; ++t) AV_BODY(lo + t)
    } else {
        for (int j = lo; j < hi; ++j) AV_BODY(j)
    }
#undef QK_BODY
#undef AV_BODY

    // --- combine halves through smem ---
    if (half == 1) {
        s_acc[pslot][lane]      = a0;
        s_acc[pslot][lane + 32] = a1;
        s_acc[pslot][lane + 64] = a2;
        s_acc[pslot][lane + 96] = a3;
    }
    __syncthreads();
    if (half == 0) {
        const float4 r0 = s_acc[pslot][lane];
        const float4 r1 = s_acc[pslot][lane + 32];
        const float4 r2 = s_acc[pslot][lane + 64];
        const float4 r3 = s_acc[pslot][lane + 96];
        float4* orow = (float4*)(out + ((size_t)b * SS + i) * DD);
        float4 o;
        o.x = a0.x + r0.x; o.y = a0.y + r0.y; o.z = a0.z + r0.z; o.w = a0.w + r0.w;
        orow[lane] = o;
        o.x = a1.x + r1.x; o.y = a1.y + r1.y; o.z = a1.z + r1.z; o.w = a1.w + r1.w;
        orow[lane + 32] = o;
        o.x = a2.x + r2.x; o.y = a2.y + r2.y; o.z = a2.z + r2.z; o.w = a2.w + r2.w;
        orow[lane + 64] = o;
        o.x = a3.x + r3.x; o.y = a3.y + r3.y; o.z = a3.z + r3.z; o.w = a3.w + r3.w;
        orow[lane + 96] = o;
    }
}

// ---------------------------------------------------------------------------
// Fill kernel: one warp per dense output row. Streams 16KB of zeros
// (evict-first float4 stores), __syncwarp (memory-ordering among lanes),
// then drops the <=32 sparse values (attn probs or mask 1.0f) in place.
// Replaces memset + scatter with a single pass at the DRAM-write roofline.
// ---------------------------------------------------------------------------
__global__ void __launch_bounds__(256)
fill_kernel(float* __restrict__ attn_out, float* __restrict__ mask_out,
            int n_attn_rows, int n_mask_rows) {
    const int w    = blockIdx.x * 8 + (threadIdx.x >> 5);
    const int lane = threadIdx.x & 31;
    const float4 z = {0.0f, 0.0f, 0.0f, 0.0f};

    if (w < n_attn_rows) {
        const int i = w & (SS - 1);
        float* base = attn_out + (size_t)w * SS;
        float4* b4 = (float4*)base;
        #pragma unroll
        for (int t = 0; t < SS / 128; ++t)
            __stcs(b4 + t * 32 + lane, z);
        __syncwarp();
        const int c = g_cnt[i];
        if (lane < c)
            base[g_cols[i * NR + lane]] = g_prob[(size_t)w * NR + lane];
    } else {
        const int r = w - n_attn_rows;
        if (r >= n_mask_rows) return;
        float* base = mask_out + (size_t)r * SS;
        float4* b4 = (float4*)base;
        #pragma unroll
        for (int t = 0; t < SS / 128; ++t)
            __stcs(b4 + t * 32 + lane, z);
        __syncwarp();
        const int c = g_cnt[r];
        if (lane < c)
            base[g_cols[r * NR + lane]] = 1.0f;
    }
}

extern "C" void kernel_launch(void* const* d_in, const int* in_sizes, int n_in,
                              void* d_out, int out_size) {
    const float* q   = (const float*)d_in[0];
    const float* k   = (const float*)d_in[1];
    const float* v   = (const float*)d_in[2];
    const void*  msk = d_in[3];
    float* out = (float*)d_out;

    const size_t OUT_N  = (size_t)BB * SS * DD;   //  8,388,608
    const size_t ATTN_N = (size_t)BB * SS * SS;   // 67,108,864
    const size_t MASK_N = (size_t)SS * SS;        // 16,777,216

    const int write_attn = (size_t)out_size >= OUT_N + ATTN_N;
    const int write_mask = (size_t)out_size >= OUT_N + ATTN_N + MASK_N;

    // Fallback for unexpected out_size shapes only (normally dead): the fill
    // kernel writes every byte of the expected attn+mask regions itself.
    if ((size_t)out_size > OUT_N &&
        (size_t)out_size != OUT_N + ATTN_N + MASK_N)
        cudaMemsetAsync(out + OUT_N, 0, ((size_t)out_size - OUT_N) * sizeof(float));

    compact_kernel<<<SS / 8, 256>>>(msk);

    attn_kernel<<<(BB * SS) / 4, 256>>>(q, k, v, out);   // 2 warps per row

    const int n_attn_rows = write_attn ? BB * SS : 0;
    const int n_mask_rows = write_mask ? SS : 0;
    const int n_rows = n_attn_rows + n_mask_rows;
    if (n_rows > 0)
        fill_kernel<<<(n_rows + 7) / 8, 256>>>(
            write_attn ? (out + OUT_N) : nullptr,
            write_mask ? (out + OUT_N + ATTN_N) : nullptr,
            n_attn_rows, n_mask_rows);
}

// round 9
// speedup vs baseline: 1.2528x; 1.2200x over previous
#include <cuda_runtime.h>
#include <cstdint>

#define BB 4
#define SS 4096
#define DD 512
#define NR 32
#define QK_SCALE 0.04419417382415922f   // 1/sqrt(512)

// Scratch (no allocations allowed).
__device__ int g_cols[SS * NR];
__device__ int g_cnt[SS];

// ---------------------------------------------------------------------------
// Mask dtype probe. Row 0 has ONLY col 0 true; row 1 has cols {0,1} true.
//  byte[4096]: 1-byte storage -> (row1,col0)=1; 4-byte storage -> row0 -> 0.
//  word[4097]: int32 -> (row1,col1)=1; f32 -> 0x3F800000.
// ---------------------------------------------------------------------------
__device__ __forceinline__ int detect_code(const unsigned char* __restrict__ m) {
    if (m[4096] == 1) return 0;
    const int* mi = (const int*)m;
    return (mi[4097] == 1) ? 1 : 2;
}

__device__ __forceinline__ unsigned nib_from_u(unsigned w) {
    unsigned m = __vsetne4(w, 0u);     // 0x01 per nonzero byte
    return (m & 1u) | ((m >> 7) & 2u) | ((m >> 14) & 4u) | ((m >> 21) & 8u);
}
__device__ __forceinline__ unsigned nib_from_i4(int4 w) {
    return (w.x ? 1u : 0u) | (w.y ? 2u : 0u) | (w.z ? 4u : 0u) | (w.w ? 8u : 0u);
}

// ---------------------------------------------------------------------------
// Mask compaction, ballot-prefix version (R8, 16.2us measured). One warp per
// row; each lane owns 16 contiguous columns -> 16-bit truth mask; lane prefix
// via 5 independent ballots + popc (no serial scan chain).
// ---------------------------------------------------------------------------
__global__ void __launch_bounds__(256)
compact_kernel(const void* __restrict__ mask) {
    const int row  = blockIdx.x * 8 + (threadIdx.x >> 5);
    const int lane = threadIdx.x & 31;
    const int code = detect_code((const unsigned char*)mask);
    const unsigned lt = (1u << lane) - 1u;

    int base = 0;
    #pragma unroll 1
    for (int it = 0; it < SS / 512; ++it) {            // 8 iters, 512 cols each
        const int col0 = it * 512 + lane * 16;
        unsigned m16;
        if (code == 0) {                               // 1-byte mask
            const uint4 wv = *(const uint4*)((const unsigned char*)mask
                                             + (size_t)row * SS + col0);
            m16 = nib_from_u(wv.x) | (nib_from_u(wv.y) << 4)
                | (nib_from_u(wv.z) << 8) | (nib_from_u(wv.w) << 12);
        } else {                                       // 4-byte mask
            const int4* mi = (const int4*)((const int*)mask + (size_t)row * SS + col0);
            m16 = nib_from_i4(mi[0]) | (nib_from_i4(mi[1]) << 4)
                | (nib_from_i4(mi[2]) << 8) | (nib_from_i4(mi[3]) << 12);
        }
        const unsigned cnt = __popc(m16);
        const unsigned b0 = __ballot_sync(0xffffffffu, cnt & 1u);
        const unsigned b1 = __ballot_sync(0xffffffffu, cnt & 2u);
        const unsigned b2 = __ballot_sync(0xffffffffu, cnt & 4u);
        const unsigned b3 = __ballot_sync(0xffffffffu, cnt & 8u);
        const unsigned b4 = __ballot_sync(0xffffffffu, cnt & 16u);
        int pos = base
                + __popc(b0 & lt) + 2 * __popc(b1 & lt) + 4 * __popc(b2 & lt)
                + 8 * __popc(b3 & lt) + 16 * __popc(b4 & lt);
        unsigned mm = m16;
        while (mm) {
            const int bb = __ffs(mm) - 1;
            if (pos < NR) g_cols[row * NR + pos] = col0 + bb;
            ++pos;
            mm &= mm - 1u;
        }
        base += __popc(b0) + 2 * __popc(b1) + 4 * __popc(b2)
              + 8 * __popc(b3) + 16 * __popc(b4);
    }
    if (lane == 0) g_cnt[row] = (base < NR) ? base : NR;
}

// ---------------------------------------------------------------------------
// Sparse attention (R4 one-warp-per-row two-pass body) + INTERLEAVED zero
// stores. Each warp owns its dense attn row: every QK iteration emits one
// streaming float4 zero-store (32 iters x 32 lanes x 16B = 16KB row), so the
// DRAM write stream is spread across the kernel instead of bursting (R2's
// mistake). After __syncwarp (memory-ordered within the warp), the warp
// scatters its own probabilities into its own row — race-free, and both the
// standalone memset and scatter kernels disappear.
// ---------------------------------------------------------------------------
__global__ void __launch_bounds__(256, 2)
attn_kernel(const float* __restrict__ q, const float* __restrict__ k,
            const float* __restrict__ v, float* __restrict__ out,
            float* __restrict__ attn_out, int write_attn) {
    const int warp  = blockIdx.x * 8 + (threadIdx.x >> 5);
    const int lane  = threadIdx.x & 31;
    const int wslot = threadIdx.x >> 5;
    const int b = warp >> 12;
    const int i = warp & (SS - 1);

    __shared__ float s_p[8][NR];
    __shared__ int   s_col[8][NR];

    const int c = g_cnt[i];
    s_col[wslot][lane] = (lane < c) ? g_cols[i * NR + lane] : 0;
    __syncwarp();

    const float4* qr = (const float4*)(q + ((size_t)b * SS + i) * DD);
    const float4 qf0 = qr[lane];
    const float4 qf1 = qr[lane + 32];
    const float4 qf2 = qr[lane + 64];
    const float4 qf3 = qr[lane + 96];

    const float4* kb = (const float4*)(k + (size_t)b * SS * DD);
    const float4* vb = (const float4*)(v + (size_t)b * SS * DD);

    float4* arow4 = (float4*)(attn_out + ((size_t)b * SS + i) * SS);
    const float4 zf4 = {0.0f, 0.0f, 0.0f, 0.0f};

#define QK_BODY(J)                                                            \
    {                                                                         \
        const int col = s_col[wslot][(J)];                                    \
        const float4* kr = kb + (size_t)col * (DD / 4);                       \
        const float4 k0 = kr[lane];                                           \
        const float4 k1 = kr[lane + 32];                                      \
        const float4 k2 = kr[lane + 64];                                      \
        const float4 k3 = kr[lane + 96];                                      \
        float d = qf0.x * k0.x + qf0.y * k0.y + qf0.z * k0.z + qf0.w * k0.w   \
                + qf1.x * k1.x + qf1.y * k1.y + qf1.z * k1.z + qf1.w * k1.w   \
                + qf2.x * k2.x + qf2.y * k2.y + qf2.z * k2.z + qf2.w * k2.w   \
                + qf3.x * k3.x + qf3.y * k3.y + qf3.z * k3.z + qf3.w * k3.w;  \
        _Pragma("unroll")                                                     \
        for (int off = 16; off; off >>= 1)                                    \
            d += __shfl_xor_sync(0xffffffffu, d, off);                        \
        if (lane == 0) s_p[wslot][(J)] = d * QK_SCALE;                        \
    }

#define AV_BODY(J)                                                            \
    {                                                                         \
        const float p = s_p[wslot][(J)];                                      \
        const float4* vr = vb + (size_t)s_col[wslot][(J)] * (DD / 4);         \
        const float4 v0 = vr[lane];                                           \
        const float4 v1 = vr[lane + 32];                                      \
        const float4 v2 = vr[lane + 64];                                      \
        const float4 v3 = vr[lane + 96];                                      \
        a0.x += p * v0.x; a0.y += p * v0.y; a0.z += p * v0.z; a0.w += p * v0.w;\
        a1.x += p * v1.x; a1.y += p * v1.y; a1.z += p * v1.z; a1.w += p * v1.w;\
        a2.x += p * v2.x; a2.y += p * v2.y; a2.z += p * v2.z; a2.w += p * v2.w;\
        a3.x += p * v3.x; a3.y += p * v3.y; a3.z += p * v3.z; a3.w += p * v3.w;\
    }

    if (write_attn) {
        if (c == 32) {
            // one interleaved zero-store per key iteration -> full 16KB row
            #pragma unroll 2
            for (int j = 0; j < 32; ++j) {
                __stcs(arow4 + j * 32 + lane, zf4);
                QK_BODY(j)
            }
        } else {
            #pragma unroll 4
            for (int t = 0; t < 32; ++t)
                __stcs(arow4 + t * 32 + lane, zf4);
            for (int j = 0; j < c; ++j) QK_BODY(j)
        }
    } else {
        if (c == 32) {
            #pragma unroll 2
            for (int j = 0; j < 32; ++j) QK_BODY(j)
        } else {
            for (int j = 0; j < c; ++j) QK_BODY(j)
        }
    }
    __syncwarp();

    // --- softmax over c (<=32) scores ---
    float m = -3.402823466e38f;
    for (int j = 0; j < c; ++j) m = fmaxf(m, s_p[wslot][j]);
    float e = (lane < c) ? __expf(s_p[wslot][lane] - m) : 0.0f;
    float sum = e;
    #pragma unroll
    for (int off = 16; off; off >>= 1)
        sum += __shfl_xor_sync(0xffffffffu, sum, off);
    const float inv = __frcp_rn(sum);
    const float p_l = e * inv;
    if (lane < c) s_p[wslot][lane] = p_l;
    __syncwarp();   // memory-orders the zero stores vs. the scatter below

    // --- scatter own probabilities over own (zeroed) row ---
    if (write_attn && lane < c)
        ((float*)arow4)[s_col[wslot][lane]] = p_l;

    // --- out = attn @ v (sparse) ---
    float4 a0 = {0,0,0,0}, a1 = {0,0,0,0}, a2 = {0,0,0,0}, a3 = {0,0,0,0};
    if (c == 32) {
        #pragma unroll 2
        for (int j = 0; j < 32; ++j) AV_BODY(j)
    } else {
        for (int j = 0; j < c; ++j) AV_BODY(j)
    }
    float4* orow = (float4*)(out + ((size_t)b * SS + i) * DD);
    orow[lane]      = a0;
    orow[lane + 32] = a1;
    orow[lane + 64] = a2;
    orow[lane + 96] = a3;
#undef QK_BODY
#undef AV_BODY
}

// ---------------------------------------------------------------------------
// Mask fill: one warp per mask row — 16KB of streaming zeros, syncwarp, then
// the <=32 ones. 67MB ~= 9us at the write roofline.
// ---------------------------------------------------------------------------
__global__ void __launch_bounds__(256)
mask_fill_kernel(float* __restrict__ mask_out) {
    const int r    = blockIdx.x * 8 + (threadIdx.x >> 5);
    const int lane = threadIdx.x & 31;
    const float4 z = {0.0f, 0.0f, 0.0f, 0.0f};
    float* base = mask_out + (size_t)r * SS;
    float4* b4 = (float4*)base;
    #pragma unroll
    for (int t = 0; t < SS / 128; ++t)
        __stcs(b4 + t * 32 + lane, z);
    __syncwarp();
    const int c = g_cnt[r];
    if (lane < c)
        base[g_cols[r * NR + lane]] = 1.0f;
}

extern "C" void kernel_launch(void* const* d_in, const int* in_sizes, int n_in,
                              void* d_out, int out_size) {
    const float* q   = (const float*)d_in[0];
    const float* k   = (const float*)d_in[1];
    const float* v   = (const float*)d_in[2];
    const void*  msk = d_in[3];
    float* out = (float*)d_out;

    const size_t OUT_N  = (size_t)BB * SS * DD;   //  8,388,608
    const size_t ATTN_N = (size_t)BB * SS * SS;   // 67,108,864
    const size_t MASK_N = (size_t)SS * SS;        // 16,777,216

    const int write_attn = (size_t)out_size >= OUT_N + ATTN_N;
    const int write_mask = (size_t)out_size >= OUT_N + ATTN_N + MASK_N;

    // Fallback for unexpected out_size shapes only (normally dead): the
    // kernels write every byte of the expected output regions themselves.
    if ((size_t)out_size > OUT_N &&
        (size_t)out_size != OUT_N + ATTN_N + MASK_N)
        cudaMemsetAsync(out + OUT_N, 0, ((size_t)out_size - OUT_N) * sizeof(float));

    compact_kernel<<<SS / 8, 256>>>(msk);

    attn_kernel<<<(BB * SS) / 8, 256>>>(
        q, k, v, out, write_attn ? (out + OUT_N) : nullptr, write_attn);

    if (write_mask)
        mask_fill_kernel<<<SS / 8, 256>>>(out + OUT_N + ATTN_N);
}

// round 10
// speedup vs baseline: 1.2951x; 1.0338x over previous
#include <cuda_runtime.h>
#include <cstdint>

#define BB 4
#define SS 4096
#define DD 512
#define NR 32
#define QK_SCALE 0.04419417382415922f   // 1/sqrt(512)

// Scratch (no allocations allowed).
__device__ int g_cols[SS * NR];
__device__ int g_cnt[SS];

// ---------------------------------------------------------------------------
// Mask dtype probe. Row 0 has ONLY col 0 true; row 1 has cols {0,1} true.
//  byte[4096]: 1-byte storage -> (row1,col0)=1; 4-byte storage -> row0 -> 0.
//  word[4097]: int32 -> (row1,col1)=1; f32 -> 0x3F800000.
// ---------------------------------------------------------------------------
__device__ __forceinline__ int detect_code(const unsigned char* __restrict__ m) {
    if (m[4096] == 1) return 0;
    const int* mi = (const int*)m;
    return (mi[4097] == 1) ? 1 : 2;
}

__device__ __forceinline__ unsigned nib_from_u(unsigned w) {
    unsigned m = __vsetne4(w, 0u);     // 0x01 per nonzero byte
    return (m & 1u) | ((m >> 7) & 2u) | ((m >> 14) & 4u) | ((m >> 21) & 8u);
}
__device__ __forceinline__ unsigned nib_from_i4(int4 w) {
    return (w.x ? 1u : 0u) | (w.y ? 2u : 0u) | (w.z ? 4u : 0u) | (w.w ? 8u : 0u);
}

// ---------------------------------------------------------------------------
// Mask compaction + fused dense mask output. One warp per row; each lane owns
// 16 contiguous columns -> 16-bit truth mask; lane prefix via 5 independent
// ballots + popc. Each iteration also streams this iteration's 2KB slice of
// the dense f32 mask row as zeros (interleaved stores — same trick that won
// in the attn kernel); after __syncwarp the warp scatters its 1.0f entries.
// Replaces the separate mask_fill kernel.
// ---------------------------------------------------------------------------
__global__ void __launch_bounds__(256)
compact_kernel(const void* __restrict__ mask,
               float* __restrict__ mask_out, int write_mask) {
    const int row  = blockIdx.x * 8 + (threadIdx.x >> 5);
    const int lane = threadIdx.x & 31;
    const int code = detect_code((const unsigned char*)mask);
    const unsigned lt = (1u << lane) - 1u;

    float4* b4m = write_mask ? (float4*)(mask_out + (size_t)row * SS) : nullptr;
    const float4 z = {0.0f, 0.0f, 0.0f, 0.0f};

    int base = 0;
    #pragma unroll 2
    for (int it = 0; it < SS / 512; ++it) {            // 8 iters, 512 cols each
        const int col0 = it * 512 + lane * 16;
        unsigned m16;
        if (code == 0) {                               // 1-byte mask
            const uint4 wv = *(const uint4*)((const unsigned char*)mask
                                             + (size_t)row * SS + col0);
            m16 = nib_from_u(wv.x) | (nib_from_u(wv.y) << 4)
                | (nib_from_u(wv.z) << 8) | (nib_from_u(wv.w) << 12);
        } else {                                       // 4-byte mask (hot path)
            const int4* mi = (const int4*)((const int*)mask + (size_t)row * SS + col0);
            m16 = nib_from_i4(mi[0]) | (nib_from_i4(mi[1]) << 4)
                | (nib_from_i4(mi[2]) << 8) | (nib_from_i4(mi[3]) << 12);
        }

        // interleaved dense-zero stores: this iter's 2KB slice of the row
        if (write_mask) {
            #pragma unroll
            for (int t = 0; t < 4; ++t)
                __stcs(b4m + it * 128 + t * 32 + lane, z);
        }

        const unsigned cnt = __popc(m16);
        const unsigned b0 = __ballot_sync(0xffffffffu, cnt & 1u);
        const unsigned b1 = __ballot_sync(0xffffffffu, cnt & 2u);
        const unsigned b2 = __ballot_sync(0xffffffffu, cnt & 4u);
        const unsigned b3 = __ballot_sync(0xffffffffu, cnt & 8u);
        const unsigned b4 = __ballot_sync(0xffffffffu, cnt & 16u);
        int pos = base
                + __popc(b0 & lt) + 2 * __popc(b1 & lt) + 4 * __popc(b2 & lt)
                + 8 * __popc(b3 & lt) + 16 * __popc(b4 & lt);
        unsigned mm = m16;
        while (mm) {
            const int bb = __ffs(mm) - 1;
            if (pos < NR) g_cols[row * NR + pos] = col0 + bb;
            ++pos;
            mm &= mm - 1u;
        }
        base += __popc(b0) + 2 * __popc(b1) + 4 * __popc(b2)
              + 8 * __popc(b3) + 16 * __popc(b4);
    }
    const int c = (base < NR) ? base : NR;
    if (lane == 0) g_cnt[row] = c;
    __syncwarp();   // order g_cols writes + zero stores before the scatter
    if (write_mask && lane < c)
        ((float*)b4m)[g_cols[row * NR + lane]] = 1.0f;
}

// ---------------------------------------------------------------------------
// Sparse attention (R9 winner, unchanged). One warp per (b, query row), two-
// pass body with one interleaved streaming zero-store per QK iteration (32
// iters x 32 lanes x 16B = warp's own 16KB dense attn row), then scatters its
// own probabilities after __syncwarp. No separate memset or scatter kernels.
// ---------------------------------------------------------------------------
__global__ void __launch_bounds__(256, 2)
attn_kernel(const float* __restrict__ q, const float* __restrict__ k,
            const float* __restrict__ v, float* __restrict__ out,
            float* __restrict__ attn_out, int write_attn) {
    const int warp  = blockIdx.x * 8 + (threadIdx.x >> 5);
    const int lane  = threadIdx.x & 31;
    const int wslot = threadIdx.x >> 5;
    const int b = warp >> 12;
    const int i = warp & (SS - 1);

    __shared__ float s_p[8][NR];
    __shared__ int   s_col[8][NR];

    const int c = g_cnt[i];
    s_col[wslot][lane] = (lane < c) ? g_cols[i * NR + lane] : 0;
    __syncwarp();

    const float4* qr = (const float4*)(q + ((size_t)b * SS + i) * DD);
    const float4 qf0 = qr[lane];
    const float4 qf1 = qr[lane + 32];
    const float4 qf2 = qr[lane + 64];
    const float4 qf3 = qr[lane + 96];

    const float4* kb = (const float4*)(k + (size_t)b * SS * DD);
    const float4* vb = (const float4*)(v + (size_t)b * SS * DD);

    float4* arow4 = (float4*)(attn_out + ((size_t)b * SS + i) * SS);
    const float4 zf4 = {0.0f, 0.0f, 0.0f, 0.0f};

#define QK_BODY(J)                                                            \
    {                                                                         \
        const int col = s_col[wslot][(J)];                                    \
        const float4* kr = kb + (size_t)col * (DD / 4);                       \
        const float4 k0 = kr[lane];                                           \
        const float4 k1 = kr[lane + 32];                                      \
        const float4 k2 = kr[lane + 64];                                      \
        const float4 k3 = kr[lane + 96];                                      \
        float d = qf0.x * k0.x + qf0.y * k0.y + qf0.z * k0.z + qf0.w * k0.w   \
                + qf1.x * k1.x + qf1.y * k1.y + qf1.z * k1.z + qf1.w * k1.w   \
                + qf2.x * k2.x + qf2.y * k2.y + qf2.z * k2.z + qf2.w * k2.w   \
                + qf3.x * k3.x + qf3.y * k3.y + qf3.z * k3.z + qf3.w * k3.w;  \
        _Pragma("unroll")                                                     \
        for (int off = 16; off; off >>= 1)                                    \
            d += __shfl_xor_sync(0xffffffffu, d, off);                        \
        if (lane == 0) s_p[wslot][(J)] = d * QK_SCALE;                        \
    }

#define AV_BODY(J)                                                            \
    {                                                                         \
        const float p = s_p[wslot][(J)];                                      \
        const float4* vr = vb + (size_t)s_col[wslot][(J)] * (DD / 4);         \
        const float4 v0 = vr[lane];                                           \
        const float4 v1 = vr[lane + 32];                                      \
        const float4 v2 = vr[lane + 64];                                      \
        const float4 v3 = vr[lane + 96];                                      \
        a0.x += p * v0.x; a0.y += p * v0.y; a0.z += p * v0.z; a0.w += p * v0.w;\
        a1.x += p * v1.x; a1.y += p * v1.y; a1.z += p * v1.z; a1.w += p * v1.w;\
        a2.x += p * v2.x; a2.y += p * v2.y; a2.z += p * v2.z; a2.w += p * v2.w;\
        a3.x += p * v3.x; a3.y += p * v3.y; a3.z += p * v3.z; a3.w += p * v3.w;\
    }

    if (write_attn) {
        if (c == 32) {
            #pragma unroll 2
            for (int j = 0; j < 32; ++j) {
                __stcs(arow4 + j * 32 + lane, zf4);
                QK_BODY(j)
            }
        } else {
            #pragma unroll 4
            for (int t = 0; t < 32; ++t)
                __stcs(arow4 + t * 32 + lane, zf4);
            for (int j = 0; j < c; ++j) QK_BODY(j)
        }
    } else {
        if (c == 32) {
            #pragma unroll 2
            for (int j = 0; j < 32; ++j) QK_BODY(j)
        } else {
            for (int j = 0; j < c; ++j) QK_BODY(j)
        }
    }
    __syncwarp();

    // --- softmax over c (<=32) scores ---
    float m = -3.402823466e38f;
    for (int j = 0; j < c; ++j) m = fmaxf(m, s_p[wslot][j]);
    float e = (lane < c) ? __expf(s_p[wslot][lane] - m) : 0.0f;
    float sum = e;
    #pragma unroll
    for (int off = 16; off; off >>= 1)
        sum += __shfl_xor_sync(0xffffffffu, sum, off);
    const float inv = __frcp_rn(sum);
    const float p_l = e * inv;
    if (lane < c) s_p[wslot][lane] = p_l;
    __syncwarp();   // memory-orders the zero stores vs. the scatter below

    if (write_attn && lane < c)
        ((float*)arow4)[s_col[wslot][lane]] = p_l;

    float4 a0 = {0,0,0,0}, a1 = {0,0,0,0}, a2 = {0,0,0,0}, a3 = {0,0,0,0};
    if (c == 32) {
        #pragma unroll 2
        for (int j = 0; j < 32; ++j) AV_BODY(j)
    } else {
        for (int j = 0; j < c; ++j) AV_BODY(j)
    }
    float4* orow = (float4*)(out + ((size_t)b * SS + i) * DD);
    orow[lane]      = a0;
    orow[lane + 32] = a1;
    orow[lane + 64] = a2;
    orow[lane + 96] = a3;
#undef QK_BODY
#undef AV_BODY
}

extern "C" void kernel_launch(void* const* d_in, const int* in_sizes, int n_in,
                              void* d_out, int out_size) {
    const float* q   = (const float*)d_in[0];
    const float* k   = (const float*)d_in[1];
    const float* v   = (const float*)d_in[2];
    const void*  msk = d_in[3];
    float* out = (float*)d_out;

    const size_t OUT_N  = (size_t)BB * SS * DD;   //  8,388,608
    const size_t ATTN_N = (size_t)BB * SS * SS;   // 67,108,864
    const size_t MASK_N = (size_t)SS * SS;        // 16,777,216

    const int write_attn = (size_t)out_size >= OUT_N + ATTN_N;
    const int write_mask = (size_t)out_size >= OUT_N + ATTN_N + MASK_N;

    // Fallback for unexpected out_size shapes only (normally dead): the
    // kernels write every byte of the expected output regions themselves.
    if ((size_t)out_size > OUT_N &&
        (size_t)out_size != OUT_N + ATTN_N + MASK_N)
        cudaMemsetAsync(out + OUT_N, 0, ((size_t)out_size - OUT_N) * sizeof(float));

    compact_kernel<<<SS / 8, 256>>>(
        msk, write_mask ? (out + OUT_N + ATTN_N) : nullptr, write_mask);

    attn_kernel<<<(BB * SS) / 8, 256>>>(
        q, k, v, out, write_attn ? (out + OUT_N) : nullptr, write_attn);
}